// round 6
// baseline (speedup 1.0000x reference)
#include <cuda_runtime.h>

// out[r][c] = posenc(X[r]) . W[3*voxel_ids[p] + c],  r = row_ids[p]
//
// Round 6 strategy: counting-sort point indices by voxel (3 tiny setup
// kernels + scatter), then main kernel = one CTA per voxel, W row (189
// floats) staged in smem, THREAD-per-point with broadcast LDS. Removes all
// W global traffic, all shuffles, and the latency chains that capped R2-R5.

#define NUM_VOXELS 512
#define NB 256            // histogram/scatter blocks
#define NMAX (1 << 18)    // N_POINTS

__device__ int g_blockhist[NUM_VOXELS * NB];   // [bin][block]
__device__ int g_blockbase[NUM_VOXELS * NB];   // excl. prefix over blocks, per bin
__device__ int g_binstart[NUM_VOXELS];
__device__ int g_bintotal[NUM_VOXELS];
__device__ int g_sorted[NMAX];

// ---- K1: per-block histogram ----
__global__ void __launch_bounds__(256)
hist_kernel(const int* __restrict__ voxel_ids, int n, int ppb)
{
    __shared__ int h[NUM_VOXELS];
    const int t = threadIdx.x, b = blockIdx.x;
    h[t] = 0; h[t + 256] = 0;
    __syncthreads();
    const int base = b * ppb;
    for (int i = t; i < ppb; i += 256) {
        int p = base + i;
        if (p < n) atomicAdd(&h[voxel_ids[p]], 1);
    }
    __syncthreads();
    g_blockhist[t * NB + b]         = h[t];
    g_blockhist[(t + 256) * NB + b] = h[t + 256];
}

// ---- K2a: per-bin exclusive scan over the NB block counts ----
__global__ void __launch_bounds__(NB)
binscan_kernel()
{
    __shared__ int sh[NB];
    const int t = threadIdx.x, bin = blockIdx.x;
    const int val = g_blockhist[bin * NB + t];
    sh[t] = val;
    __syncthreads();
#pragma unroll
    for (int off = 1; off < NB; off <<= 1) {
        int x = sh[t];
        if (t >= off) x += sh[t - off];
        __syncthreads();
        sh[t] = x;
        __syncthreads();
    }
    g_blockbase[bin * NB + t] = sh[t] - val;       // exclusive
    if (t == NB - 1) g_bintotal[bin] = sh[t];
}

// ---- K2b: exclusive scan over the 512 bin totals ----
__global__ void __launch_bounds__(NUM_VOXELS)
totalscan_kernel()
{
    __shared__ int sh[NUM_VOXELS];
    const int t = threadIdx.x;
    const int val = g_bintotal[t];
    sh[t] = val;
    __syncthreads();
#pragma unroll
    for (int off = 1; off < NUM_VOXELS; off <<= 1) {
        int x = sh[t];
        if (t >= off) x += sh[t - off];
        __syncthreads();
        sh[t] = x;
        __syncthreads();
    }
    g_binstart[t] = sh[t] - val;
}

// ---- K3: scatter point indices into voxel-sorted order ----
__global__ void __launch_bounds__(256)
scatter_kernel(const int* __restrict__ voxel_ids, int n, int ppb)
{
    __shared__ int cur[NUM_VOXELS];
    const int t = threadIdx.x, b = blockIdx.x;
    cur[t]       = g_binstart[t]       + g_blockbase[t * NB + b];
    cur[t + 256] = g_binstart[t + 256] + g_blockbase[(t + 256) * NB + b];
    __syncthreads();
    const int base = b * ppb;
    for (int i = t; i < ppb; i += 256) {
        int p = base + i;
        if (p < n) {
            int pos = atomicAdd(&cur[voxel_ids[p]], 1);
            g_sorted[pos] = p;
        }
    }
}

// ---- K4: main — one CTA per voxel, W in smem, thread-per-point ----
__global__ void __launch_bounds__(256)
voxel_main_kernel(const float* __restrict__ X,
                  const float* __restrict__ W,
                  const int* __restrict__ row_ids,
                  float* __restrict__ out)
{
    __shared__ float Wsh[3 * 64];   // rows padded to 64
    const int v = blockIdx.x;
    const int t = threadIdx.x;

    // stage this voxel's 3x63 weight block
    for (int i = t; i < 189; i += 256) {
        int c = i / 63, j = i - 63 * c;
        Wsh[c * 64 + j] = W[(3 * v + c) * 63 + j];
    }
    __syncthreads();

    const int start = g_binstart[v];
    const int cnt   = g_bintotal[v];
    const float* __restrict__ W0 = Wsh;
    const float* __restrict__ W1 = Wsh + 64;
    const float* __restrict__ W2 = Wsh + 128;

    for (int i = t; i < cnt; i += 256) {
        const int p = g_sorted[start + i];
        const int r = row_ids[p];
        const float x0 = X[3 * r + 0];
        const float x1 = X[3 * r + 1];
        const float x2 = X[3 * r + 2];

        // raw x channels (posenc cols 0..2)
        float a0 = x0 * W0[0]; a0 = fmaf(x1, W0[1], a0); a0 = fmaf(x2, W0[2], a0);
        float a1 = x0 * W1[0]; a1 = fmaf(x1, W1[1], a1); a1 = fmaf(x2, W1[2], a1);
        float a2 = x0 * W2[0]; a2 = fmaf(x1, W2[1], a2); a2 = fmaf(x2, W2[2], a2);

#pragma unroll
        for (int f = 0; f < 10; ++f) {
            const float sc = (float)(1 << f);
            const int jb = 3 + 6 * f;     // sin cols jb+d, cos cols jb+3+d
            float s, c;
            __sincosf(x0 * sc, &s, &c);
            a0 = fmaf(s, W0[jb + 0], a0); a0 = fmaf(c, W0[jb + 3], a0);
            a1 = fmaf(s, W1[jb + 0], a1); a1 = fmaf(c, W1[jb + 3], a1);
            a2 = fmaf(s, W2[jb + 0], a2); a2 = fmaf(c, W2[jb + 3], a2);
            __sincosf(x1 * sc, &s, &c);
            a0 = fmaf(s, W0[jb + 1], a0); a0 = fmaf(c, W0[jb + 4], a0);
            a1 = fmaf(s, W1[jb + 1], a1); a1 = fmaf(c, W1[jb + 4], a1);
            a2 = fmaf(s, W2[jb + 1], a2); a2 = fmaf(c, W2[jb + 4], a2);
            __sincosf(x2 * sc, &s, &c);
            a0 = fmaf(s, W0[jb + 2], a0); a0 = fmaf(c, W0[jb + 5], a0);
            a1 = fmaf(s, W1[jb + 2], a1); a1 = fmaf(c, W1[jb + 5], a1);
            a2 = fmaf(s, W2[jb + 2], a2); a2 = fmaf(c, W2[jb + 5], a2);
        }

        out[3 * r + 0] = a0;
        out[3 * r + 1] = a1;
        out[3 * r + 2] = a2;
    }
}

extern "C" void kernel_launch(void* const* d_in, const int* in_sizes, int n_in,
                              void* d_out, int out_size)
{
    const float* X         = (const float*)d_in[0];
    const float* W         = (const float*)d_in[1];
    const int*   row_ids   = (const int*)d_in[2];
    const int*   voxel_ids = (const int*)d_in[3];
    float*       out       = (float*)d_out;

    const int n   = in_sizes[0] / 3;          // N_POINTS
    const int ppb = (n + NB - 1) / NB;

    hist_kernel<<<NB, 256>>>(voxel_ids, n, ppb);
    binscan_kernel<<<NUM_VOXELS, NB>>>();
    totalscan_kernel<<<1, NUM_VOXELS>>>();
    scatter_kernel<<<NB, 256>>>(voxel_ids, n, ppb);
    voxel_main_kernel<<<NUM_VOXELS, 256>>>(X, W, row_ids, out);
}

// round 7
// speedup vs baseline: 1.1405x; 1.1405x over previous
#include <cuda_runtime.h>

// out[r][c] = posenc(X[r]) . W[3*voxel_ids[p] + c],  r = row_ids[p]
//
// Pipeline:
//  K1 rank:    pos[p] = atomicAdd(cnt[voxel_ids[p]], 1)   (counters 128B-strided)
//  K2 scan:    binstart = exclusive_scan(cnt); cnt = 0 (self-reset for graph replay)
//  K3 scatter: g_pts[binstart[v]+pos[p]] = float4(x0,x1,x2,bits(row_ids[p]))
//  K4 main:    CTA per voxel; W (3x63) staged as float4 in smem; thread-per-point;
//              input fully coalesced, weights broadcast LDS.128, no shuffles.

#define NUM_VOXELS 512
#define NPTS_MAX (1 << 18)
#define PAD 32                    // counter stride in ints = 128 B

__device__ int    g_cnt[NUM_VOXELS * PAD];   // zero-init; self-reset by K2
__device__ int    g_pos[NPTS_MAX];
__device__ int    g_binstart[NUM_VOXELS + 1];
__device__ float4 g_pts[NPTS_MAX];

// ---- K1: per-point rank within its voxel ----
__global__ void __launch_bounds__(256)
rank_kernel(const int* __restrict__ voxel_ids, int n)
{
    int p = blockIdx.x * 256 + threadIdx.x;
    if (p >= n) return;
    g_pos[p] = atomicAdd(&g_cnt[voxel_ids[p] * PAD], 1);
}

// ---- K2: scan 512 counts -> binstart, zero counters ----
__global__ void __launch_bounds__(NUM_VOXELS)
scan_kernel(int n)
{
    __shared__ int sh[NUM_VOXELS];
    const int t = threadIdx.x;
    const int val = g_cnt[t * PAD];
    g_cnt[t * PAD] = 0;                  // reset for next graph replay
    sh[t] = val;
    __syncthreads();
#pragma unroll
    for (int off = 1; off < NUM_VOXELS; off <<= 1) {
        int x = sh[t];
        if (t >= off) x += sh[t - off];
        __syncthreads();
        sh[t] = x;
        __syncthreads();
    }
    g_binstart[t] = sh[t] - val;         // exclusive
    if (t == NUM_VOXELS - 1) g_binstart[NUM_VOXELS] = n;
}

// ---- K3: scatter payload into voxel-sorted order ----
__global__ void __launch_bounds__(256)
scatter_kernel(const float* __restrict__ X,
               const int* __restrict__ row_ids,
               const int* __restrict__ voxel_ids,
               int n)
{
    int p = blockIdx.x * 256 + threadIdx.x;
    if (p >= n) return;
    const int v = voxel_ids[p];
    const int dst = g_binstart[v] + g_pos[p];
    const int r = row_ids[p];
    float4 pay;
    pay.x = X[3 * r + 0];
    pay.y = X[3 * r + 1];
    pay.z = X[3 * r + 2];
    pay.w = __int_as_float(r);
    g_pts[dst] = pay;
}

// ---- K4: main — CTA per voxel, W in smem (float4, padded to 64/row) ----
__global__ void __launch_bounds__(256)
voxel_main_kernel(const float* __restrict__ W,
                  float* __restrict__ out)
{
    __shared__ float4 Wsh[3 * 16];       // [channel][16 float4] = 64 floats/row
    const int v = blockIdx.x;
    const int t = threadIdx.x;

    // stage 3x63 weights, pad to 64
    if (t < 192) {
        int c = t >> 6, j = t & 63;
        ((float*)Wsh)[t] = (j < 63) ? W[(3 * v + c) * 63 + j] : 0.0f;
    }
    __syncthreads();

    const int start = g_binstart[v];
    const int cnt   = g_binstart[v + 1] - start;

    for (int i = t; i < cnt; i += 256) {
        const float4 pay = g_pts[start + i];
        const float x0 = pay.x, x1 = pay.y, x2 = pay.z;
        const int   r  = __float_as_int(pay.w);

        // build the 63-channel encoding in registers (col = 3 + 6f + 3s + d)
        float e[64];
        e[0] = x0; e[1] = x1; e[2] = x2; e[63] = 0.0f;
#pragma unroll
        for (int f = 0; f < 10; ++f) {
            const float sc = (float)(1 << f);
            const int jb = 3 + 6 * f;
            float s, c;
            __sincosf(x0 * sc, &s, &c); e[jb + 0] = s; e[jb + 3] = c;
            __sincosf(x1 * sc, &s, &c); e[jb + 1] = s; e[jb + 4] = c;
            __sincosf(x2 * sc, &s, &c); e[jb + 2] = s; e[jb + 5] = c;
        }

        float acc[3];
#pragma unroll
        for (int c = 0; c < 3; ++c) {
            float a = 0.0f;
#pragma unroll
            for (int q = 0; q < 16; ++q) {
                const float4 w = Wsh[c * 16 + q];
                a = fmaf(e[4 * q + 0], w.x, a);
                a = fmaf(e[4 * q + 1], w.y, a);
                a = fmaf(e[4 * q + 2], w.z, a);
                a = fmaf(e[4 * q + 3], w.w, a);
            }
            acc[c] = a;
        }

        out[3 * r + 0] = acc[0];
        out[3 * r + 1] = acc[1];
        out[3 * r + 2] = acc[2];
    }
}

extern "C" void kernel_launch(void* const* d_in, const int* in_sizes, int n_in,
                              void* d_out, int out_size)
{
    const float* X         = (const float*)d_in[0];
    const float* W         = (const float*)d_in[1];
    const int*   row_ids   = (const int*)d_in[2];
    const int*   voxel_ids = (const int*)d_in[3];
    float*       out       = (float*)d_out;

    const int n = in_sizes[0] / 3;               // N_POINTS
    const int nb = (n + 255) / 256;

    rank_kernel<<<nb, 256>>>(voxel_ids, n);
    scan_kernel<<<1, NUM_VOXELS>>>(n);
    scatter_kernel<<<nb, 256>>>(X, row_ids, voxel_ids, n);
    voxel_main_kernel<<<NUM_VOXELS, 256>>>(W, out);
}